// round 1
// baseline (speedup 1.0000x reference)
#include <cuda_runtime.h>

#define NB      4096        // batch (selection axis)
#define NT      256         // T
#define ND      64          // D
#define G       4           // columns per block
#define NCOL    (NT * ND)   // 16384 columns per tensor
#define KRANK   204         // int(0.05 * 4096)
#define NTHREADS 128

__device__ float g_var[2 * NCOL];

static __device__ __forceinline__ unsigned key_of(float f) {
    unsigned u = __float_as_uint(f);
    unsigned mask = (unsigned)((int)u >> 31) | 0x80000000u;
    return u ^ mask;  // monotone: key order == float ascending order
}
static __device__ __forceinline__ float float_of(unsigned k) {
    unsigned mask = (k & 0x80000000u) ? 0x80000000u : 0xFFFFFFFFu;
    return __uint_as_float(k ^ mask);
}
// swizzled smem word address for (column j, position i): conflict-free for
// both the load-phase stores (lanes = consecutive i, j fixed) and the
// select-phase column scans (lanes = consecutive i within one column).
static __device__ __forceinline__ int sw_addr(int j, int i) {
    return i * G + (j ^ ((i >> 3) & 3));
}

__global__ void __launch_bounds__(NTHREADS, 2)
select_kernel(const float* __restrict__ xf, const float* __restrict__ xr) {
    extern __shared__ unsigned smem[];
    unsigned* keys = smem;            // NB*G = 16384 words (64 KB)
    unsigned* hist = smem + NB * G;   // 4 warps * 4 cols * 256 bins (16 KB)

    const int tid  = threadIdx.x;
    const int lane = tid & 31;
    const int w    = tid >> 5;

    const int bid    = blockIdx.x;
    const int tensor = bid >> 12;       // 8192 blocks total
    const int rem    = bid & 4095;
    const int t      = rem >> 4;
    const int dg     = rem & 15;

    const float* src = tensor ? xr : xf;
    const float4* p  = reinterpret_cast<const float4*>(src) + (t * 16 + dg);

    // zero this warp's histogram region (4 cols * 256 bins)
    #pragma unroll
    for (int i = 0; i < 32; i++) hist[w * 1024 + i * 32 + lane] = 0;
    __syncwarp();

    unsigned* myhist = hist + w * 1024;

    // ---- load + key transform + pass-1 (top byte) histogram, 8-deep MLP ----
    #pragma unroll 1
    for (int base = 0; base < 32; base += 8) {
        float4 buf[8];
        #pragma unroll
        for (int u = 0; u < 8; u++) {
            int b = (base + u) * NTHREADS + tid;
            buf[u] = __ldg(p + (size_t)b * (NCOL / 4));
        }
        #pragma unroll
        for (int u = 0; u < 8; u++) {
            int b = (base + u) * NTHREADS + tid;
            float vv[4] = {buf[u].x, buf[u].y, buf[u].z, buf[u].w};
            #pragma unroll
            for (int j = 0; j < 4; j++) {
                unsigned key = key_of(vv[j]);
                keys[sw_addr(j, b)] = key;
                unsigned bin = key >> 24;
                // atomics-free per-warp histogram: leaders of equal-bin groups
                // write distinct addresses -> race-free within the warp.
                unsigned peers = __match_any_sync(0xffffffffu, bin);
                if (lane == (__ffs(peers) - 1))
                    myhist[j * 256 + bin] += __popc(peers);
            }
        }
    }
    __syncthreads();

    // ---- select phase: warp w owns column j = w ----
    const int j = w;
    int k = KRANK;

    // merge the 4 per-warp pass-1 histograms; lane holds bins [lane*8, lane*8+8)
    unsigned c[8];
    #pragma unroll
    for (int i = 0; i < 8; i++) {
        int bin = lane * 8 + i;
        unsigned s = 0;
        #pragma unroll
        for (int ww = 0; ww < 4; ww++) s += hist[ww * 1024 + j * 256 + bin];
        c[i] = s;
    }
    __syncthreads();  // all merges done before hist region is reused as scratch

    // find bucket containing rank k; update k to rank-within-bucket
    auto find_bucket = [&](unsigned cc[8], int& kk) -> unsigned {
        unsigned lanesum = 0;
        #pragma unroll
        for (int i = 0; i < 8; i++) lanesum += cc[i];
        unsigned s = lanesum;
        #pragma unroll
        for (int off = 1; off < 32; off <<= 1) {
            unsigned n = __shfl_up_sync(0xffffffffu, s, off);
            if (lane >= off) s += n;
        }
        unsigned run = s - lanesum;  // exclusive prefix over lanes
        int bucket = -1, nk = 0;
        #pragma unroll
        for (int i = 0; i < 8; i++) {
            if (bucket < 0 && (unsigned)kk >= run && (unsigned)kk < run + cc[i]) {
                bucket = lane * 8 + i;
                nk = kk - (int)run;
            }
            run += cc[i];
        }
        unsigned bal = __ballot_sync(0xffffffffu, bucket >= 0);
        int srcl = __ffs(bal) - 1;
        int bb = __shfl_sync(0xffffffffu, bucket, srcl);
        kk = __shfl_sync(0xffffffffu, nk, srcl);
        return (unsigned)bb;
    };

    // compact elements whose byte at `shift` equals `b` to the front (in place,
    // warp-synchronous; writes never pass the read frontier)
    auto compact = [&](int cnt_in, int shift, unsigned b) -> int {
        int wpos = 0;
        int nit = (cnt_in + 31) >> 5;
        for (int itn = 0; itn < nit; itn++) {
            int i = itn * 32 + lane;
            unsigned key = 0;
            bool ok = false;
            if (i < cnt_in) {
                key = keys[sw_addr(j, i)];
                ok = ((key >> shift) & 255u) == b;
            }
            unsigned m = __ballot_sync(0xffffffffu, ok);
            if (ok)
                keys[sw_addr(j, wpos + __popc(m & ((1u << lane) - 1)))] = key;
            wpos += __popc(m);
        }
        return wpos;
    };

    unsigned bucket = find_bucket(c, k);
    unsigned prefix = bucket << 24;
    int cnt = compact(NB, 24, bucket);

    unsigned* h = hist + w * 1024;  // per-warp 256-bin scratch
    for (int shift = 16; shift >= 0; shift -= 8) {
        #pragma unroll
        for (int i = 0; i < 8; i++) h[lane + i * 32] = 0;
        __syncwarp();
        int nit = (cnt + 31) >> 5;
        for (int itn = 0; itn < nit; itn++) {
            int i = itn * 32 + lane;
            bool a = i < cnt;
            unsigned key = a ? keys[sw_addr(j, i)] : 0u;
            unsigned m = __ballot_sync(0xffffffffu, a);
            if (a) {
                unsigned bin = (key >> shift) & 255u;
                unsigned peers = __match_any_sync(m, bin);
                if (lane == (__ffs(peers) - 1)) h[bin] += __popc(peers);
            }
        }
        __syncwarp();
        #pragma unroll
        for (int i = 0; i < 8; i++) c[i] = h[lane * 8 + i];
        bucket = find_bucket(c, k);
        prefix |= bucket << shift;
        if (shift > 0) cnt = compact(cnt, shift, bucket);
    }

    if (lane == 0)
        g_var[tensor * NCOL + t * ND + dg * G + j] = float_of(prefix);
}

__global__ void reduce_kernel(float* __restrict__ out) {
    __shared__ double sa[256], sr[256];
    int tid = threadIdx.x;
    double a = 0.0, r = 0.0;
    for (int i = tid; i < NCOL; i += 256) {
        float vf = g_var[i];
        float vr = g_var[NCOL + i];
        float d  = fabsf(vf - vr);
        a += (double)d;
        r += (double)(d / (fabsf(vr) + 1e-8f));
    }
    sa[tid] = a; sr[tid] = r;
    __syncthreads();
    for (int s = 128; s > 0; s >>= 1) {
        if (tid < s) { sa[tid] += sa[tid + s]; sr[tid] += sr[tid + s]; }
        __syncthreads();
    }
    if (tid == 0) {
        out[0] = (float)(sa[0] / (double)NCOL);
        out[1] = (float)(sr[0] / (double)NCOL);
    }
}

extern "C" void kernel_launch(void* const* d_in, const int* in_sizes, int n_in,
                              void* d_out, int out_size) {
    const float* xf = (const float*)d_in[0];
    const float* xr = (const float*)d_in[1];
    const int smem_bytes = (NB * G + 4 * G * 256) * 4;  // 81920
    cudaFuncSetAttribute(select_kernel,
                         cudaFuncAttributeMaxDynamicSharedMemorySize, smem_bytes);
    select_kernel<<<2 * NT * (ND / G), NTHREADS, smem_bytes>>>(xf, xr);
    reduce_kernel<<<1, 256>>>((float*)d_out);
}

// round 2
// speedup vs baseline: 3.9470x; 3.9470x over previous
#include <cuda_runtime.h>

#define NB       4096        // batch (selection axis)
#define NT       256         // T
#define ND       64          // D
#define NCOL     (NT * ND)   // 16384 columns per tensor
#define KRANK    204         // int(0.05 * 4096), 0-based rank
#define G        16          // columns per block (4 float4 columns = 64 B/row)
#define CAP      88          // candidate capacity per (column, warp) segment
#define NTHREADS 256
#define NWARP    8

__device__ float g_var[2 * NCOL];

static __device__ __forceinline__ unsigned key_of(float f) {
    unsigned u = __float_as_uint(f);
    unsigned mask = (unsigned)((int)u >> 31) | 0x80000000u;
    return u ^ mask;  // monotone: key order == float ascending order
}
static __device__ __forceinline__ float float_of(unsigned k) {
    unsigned mask = (k & 0x80000000u) ? 0x80000000u : 0xFFFFFFFFu;
    return __uint_as_float(k ^ mask);
}

// find the 256-bin bucket containing 0-based rank k; k becomes rank-in-bucket.
// cc[i] = count of bin (lane*8 + i). Warp-collective.
static __device__ __forceinline__ unsigned find_bucket(const unsigned cc[8], int& kk, int lane) {
    unsigned lanesum = 0;
    #pragma unroll
    for (int i = 0; i < 8; i++) lanesum += cc[i];
    unsigned s = lanesum;
    #pragma unroll
    for (int off = 1; off < 32; off <<= 1) {
        unsigned n = __shfl_up_sync(0xffffffffu, s, off);
        if (lane >= off) s += n;
    }
    unsigned run = s - lanesum;  // exclusive prefix over lanes
    int bucket = -1, nk = 0;
    #pragma unroll
    for (int i = 0; i < 8; i++) {
        if (bucket < 0 && (unsigned)kk >= run && (unsigned)kk < run + cc[i]) {
            bucket = lane * 8 + i;
            nk = kk - (int)run;
        }
        run += cc[i];
    }
    unsigned bal = __ballot_sync(0xffffffffu, bucket >= 0);
    int srcl = __ffs(bal) - 1;
    int bb = __shfl_sync(0xffffffffu, bucket, srcl);
    kk = __shfl_sync(0xffffffffu, nk, srcl);
    return (unsigned)bb;
}

__global__ void __launch_bounds__(NTHREADS, 4)
select_kernel(const float* __restrict__ xf, const float* __restrict__ xr) {
    extern __shared__ unsigned smem[];
    unsigned* seg  = smem;                        // [G][NWARP][CAP]
    unsigned* cnt  = smem + G * NWARP * CAP;      // [G][NWARP]
    unsigned* hist = cnt + G * NWARP;             // [NWARP][256]

    const int tid  = threadIdx.x;
    const int lane = tid & 31;
    const int w    = tid >> 5;

    const int bid    = blockIdx.x;                // 2048 blocks
    const int tensor = bid >> 10;
    const int rem    = bid & 1023;
    const int t      = rem >> 2;
    const int dgrp   = rem & 3;                   // which group of 16 columns

    const float* src = tensor ? xr : xf;
    // this thread's float4-column within the block's 4 float4 columns
    const int c = tid & 3;
    const float4* p = reinterpret_cast<const float4*>(src) + (t * 16 + dgrp * 4 + c);

    const unsigned THRKEY   = key_of(-1.45f);     // compile-time constant
    const unsigned grpmask  = 0x11111111u << c;   // lanes with same c in this warp
    const unsigned lmlt     = (1u << lane) - 1u;

    unsigned wcnt[4] = {0, 0, 0, 0};              // counts for cols c*4+jj (uniform in group)

    // ---- streaming load + candidate capture (no atomics, no per-element MATCH) ----
    #pragma unroll 1
    for (int it = 0; it < 64; it += 4) {
        float4 buf[4];
        #pragma unroll
        for (int u = 0; u < 4; u++) {
            int r = (it + u) * 64 + (tid >> 2);
            buf[u] = __ldg(p + (size_t)r * (NCOL / 4));
        }
        #pragma unroll
        for (int u = 0; u < 4; u++) {
            float vv[4] = {buf[u].x, buf[u].y, buf[u].z, buf[u].w};
            #pragma unroll
            for (int jj = 0; jj < 4; jj++) {
                unsigned key = key_of(vv[jj]);
                bool pred = key < THRKEY;
                unsigned bal = __ballot_sync(0xffffffffu, pred);
                unsigned mc  = bal & grpmask;
                if (pred) {
                    int col  = c * 4 + jj;
                    int slot = (int)wcnt[jj] + __popc(mc & lmlt);
                    if (slot < CAP)
                        seg[(col * NWARP + w) * CAP + slot] = key;
                }
                wcnt[jj] += __popc(mc);
            }
        }
    }
    if (lane < 4) {  // lane l is leader of group c=l; all group lanes hold same counts
        #pragma unroll
        for (int jj = 0; jj < 4; jj++)
            cnt[(lane * 4 + jj) * NWARP + w] = wcnt[jj];
    }
    __syncthreads();

    // ---- select: warp w owns columns w and w+8 ----
    unsigned* h = hist + w * 256;

    for (int cc2 = 0; cc2 < 2; cc2++) {
        const int col = w + cc2 * NWARP;
        unsigned* colb = seg + col * NWARP * CAP;

        int total = 0;
        bool ovf = false;
        int cs_arr[NWARP];
        #pragma unroll
        for (int s = 0; s < NWARP; s++) {
            int cs = (int)cnt[col * NWARP + s];
            if (cs > CAP) ovf = true;
            cs_arr[s] = cs < CAP ? cs : CAP;
            total += cs;
        }

        unsigned prefix = 0;
        int k = KRANK;

        if (!ovf && total > KRANK) {
            // pass 1: histogram of top byte over segmented candidates
            #pragma unroll
            for (int i = 0; i < 8; i++) h[i * 32 + lane] = 0;
            __syncwarp();
            for (int s = 0; s < NWARP; s++) {
                int cs = cs_arr[s];
                for (int i0 = 0; i0 < cs; i0 += 32) {
                    int i = i0 + lane;
                    bool a = i < cs;
                    unsigned key = a ? colb[s * CAP + i] : 0u;
                    unsigned m = __ballot_sync(0xffffffffu, a);
                    if (a) {
                        unsigned bin = key >> 24;
                        unsigned peers = __match_any_sync(m, bin);
                        if (lane == __ffs(peers) - 1) h[bin] += __popc(peers);
                    }
                }
            }
            __syncwarp();
            unsigned c8[8];
            #pragma unroll
            for (int i = 0; i < 8; i++) c8[i] = h[lane * 8 + i];
            unsigned bucket = find_bucket(c8, k, lane);
            prefix = bucket << 24;

            // filtered compaction: segments -> flat [colb, cntf)
            int wpos = 0;
            for (int s = 0; s < NWARP; s++) {
                int cs = cs_arr[s];
                for (int i0 = 0; i0 < cs; i0 += 32) {
                    int i = i0 + lane;
                    bool a = i < cs;
                    unsigned key = a ? colb[s * CAP + i] : 0u;
                    bool ok = a && ((key >> 24) == bucket);
                    unsigned m = __ballot_sync(0xffffffffu, ok);  // sync: reads before writes
                    if (ok) colb[wpos + __popc(m & lmlt)] = key;
                    wpos += __popc(m);
                }
            }
            int cntf = wpos;

            // passes 2..4 on flat array
            for (int shift = 16; shift >= 0; shift -= 8) {
                #pragma unroll
                for (int i = 0; i < 8; i++) h[i * 32 + lane] = 0;
                __syncwarp();
                for (int i0 = 0; i0 < cntf; i0 += 32) {
                    int i = i0 + lane;
                    bool a = i < cntf;
                    unsigned key = a ? colb[i] : 0u;
                    unsigned m = __ballot_sync(0xffffffffu, a);
                    if (a) {
                        unsigned bin = (key >> shift) & 255u;
                        unsigned peers = __match_any_sync(m, bin);
                        if (lane == __ffs(peers) - 1) h[bin] += __popc(peers);
                    }
                }
                __syncwarp();
                #pragma unroll
                for (int i = 0; i < 8; i++) c8[i] = h[lane * 8 + i];
                bucket = find_bucket(c8, k, lane);
                prefix |= bucket << shift;
                if (shift > 0) {
                    int np = 0;
                    for (int i0 = 0; i0 < cntf; i0 += 32) {
                        int i = i0 + lane;
                        bool a = i < cntf;
                        unsigned key = a ? colb[i] : 0u;
                        bool ok = a && (((key >> shift) & 255u) == bucket);
                        unsigned m = __ballot_sync(0xffffffffu, ok);
                        if (ok) colb[np + __popc(m & lmlt)] = key;
                        np += __popc(m);
                    }
                    cntf = np;
                }
            }
        } else {
            // exact fallback (rare): 4-pass radix select re-reading the column
            const int cglob = t * 64 + dgrp * 16 + col;
            for (int shift = 24; shift >= 0; shift -= 8) {
                #pragma unroll
                for (int i = 0; i < 8; i++) h[i * 32 + lane] = 0;
                __syncwarp();
                for (int i = lane; i < NB; i += 32) {
                    unsigned key = key_of(__ldg(src + (size_t)i * NCOL + cglob));
                    bool act = (shift == 24) ||
                               ((key >> (shift + 8)) == (prefix >> (shift + 8)));
                    unsigned m = __ballot_sync(0xffffffffu, act);
                    if (act) {
                        unsigned bin = (key >> shift) & 255u;
                        unsigned peers = __match_any_sync(m, bin);
                        if (lane == __ffs(peers) - 1) h[bin] += __popc(peers);
                    }
                }
                __syncwarp();
                unsigned c8[8];
                #pragma unroll
                for (int i = 0; i < 8; i++) c8[i] = h[lane * 8 + i];
                unsigned bucket = find_bucket(c8, k, lane);
                prefix |= bucket << shift;
            }
        }

        if (lane == 0)
            g_var[tensor * NCOL + t * ND + dgrp * G + col] = float_of(prefix);
    }
}

__global__ void reduce_kernel(float* __restrict__ out) {
    const int tid  = threadIdx.x;
    const int lane = tid & 31;
    const int wid  = tid >> 5;
    double a = 0.0, r = 0.0;
    #pragma unroll
    for (int u = 0; u < 16; u++) {
        int i = u * 1024 + tid;
        float vf = g_var[i];
        float vr = g_var[NCOL + i];
        float d  = fabsf(vf - vr);
        a += (double)d;
        r += (double)(d / (fabsf(vr) + 1e-8f));
    }
    #pragma unroll
    for (int off = 16; off > 0; off >>= 1) {
        a += __shfl_down_sync(0xffffffffu, a, off);
        r += __shfl_down_sync(0xffffffffu, r, off);
    }
    __shared__ double sa[32], sr[32];
    if (lane == 0) { sa[wid] = a; sr[wid] = r; }
    __syncthreads();
    if (tid < 32) {
        a = sa[tid]; r = sr[tid];
        #pragma unroll
        for (int off = 16; off > 0; off >>= 1) {
            a += __shfl_down_sync(0xffffffffu, a, off);
            r += __shfl_down_sync(0xffffffffu, r, off);
        }
        if (tid == 0) {
            out[0] = (float)(a / (double)NCOL);
            out[1] = (float)(r / (double)NCOL);
        }
    }
}

extern "C" void kernel_launch(void* const* d_in, const int* in_sizes, int n_in,
                              void* d_out, int out_size) {
    const float* xf = (const float*)d_in[0];
    const float* xr = (const float*)d_in[1];
    const int smem_bytes = (G * NWARP * CAP + G * NWARP + NWARP * 256) * 4;  // 53760
    cudaFuncSetAttribute(select_kernel,
                         cudaFuncAttributeMaxDynamicSharedMemorySize, smem_bytes);
    select_kernel<<<2 * NT * (ND / G), NTHREADS, smem_bytes>>>(xf, xr);
    reduce_kernel<<<1, 1024>>>((float*)d_out);
}

// round 3
// speedup vs baseline: 5.8674x; 1.4866x over previous
#include <cuda_runtime.h>

#define NB       4096        // batch (selection axis)
#define NT       256         // T
#define ND       64          // D
#define NCOL     (NT * ND)   // 16384 columns per tensor
#define KRANK    204         // int(0.05 * 4096), 0-based rank
#define G        16          // columns per block (4 float4 columns = 64 B/row)
#define CAPC     448         // flat candidate capacity per column (mean 301, sd 16.7)
#define NTHREADS 256
#define NWARP    8

__device__ float  g_var[2 * NCOL];
__device__ double g_pa[16];
__device__ double g_pr[16];

static __device__ __forceinline__ unsigned key_of(float f) {
    unsigned u = __float_as_uint(f);
    unsigned mask = (unsigned)((int)u >> 31) | 0x80000000u;
    return u ^ mask;  // monotone: key order == float ascending order
}
static __device__ __forceinline__ float float_of(unsigned k) {
    unsigned mask = (k & 0x80000000u) ? 0x80000000u : 0xFFFFFFFFu;
    return __uint_as_float(k ^ mask);
}

// find the 256-bin bucket containing 0-based rank k; k becomes rank-in-bucket.
// cc[i] = count of bin (lane*8 + i). Warp-collective.
static __device__ __forceinline__ unsigned find_bucket(const unsigned cc[8], int& kk, int lane) {
    unsigned lanesum = 0;
    #pragma unroll
    for (int i = 0; i < 8; i++) lanesum += cc[i];
    unsigned s = lanesum;
    #pragma unroll
    for (int off = 1; off < 32; off <<= 1) {
        unsigned n = __shfl_up_sync(0xffffffffu, s, off);
        if (lane >= off) s += n;
    }
    unsigned run = s - lanesum;  // exclusive prefix over lanes
    int bucket = -1, nk = 0;
    #pragma unroll
    for (int i = 0; i < 8; i++) {
        if (bucket < 0 && (unsigned)kk >= run && (unsigned)kk < run + cc[i]) {
            bucket = lane * 8 + i;
            nk = kk - (int)run;
        }
        run += cc[i];
    }
    unsigned bal = __ballot_sync(0xffffffffu, bucket >= 0);
    int srcl = __ffs(bal) - 1;
    int bb = __shfl_sync(0xffffffffu, bucket, srcl);
    kk = __shfl_sync(0xffffffffu, nk, srcl);
    return (unsigned)bb;
}

__global__ void __launch_bounds__(NTHREADS, 4)
select_kernel(const float* __restrict__ xf, const float* __restrict__ xr) {
    extern __shared__ unsigned smem[];
    unsigned* seg  = smem;                       // [G][CAPC]  flat per-column candidates
    unsigned* scnt = smem + G * CAPC;            // [G]
    unsigned* hist = scnt + G;                   // [NWARP][256]

    const int tid  = threadIdx.x;
    const int lane = tid & 31;
    const int w    = tid >> 5;

    const int bid    = blockIdx.x;               // 2048 blocks
    const int tensor = bid >> 10;
    const int rem    = bid & 1023;
    const int t      = rem >> 2;
    const int dgrp   = rem & 3;                  // which group of 16 columns

    const float* src = tensor ? xr : xf;
    const int c = tid & 3;                       // this thread's float4-column (0..3)
    const float4* p = reinterpret_cast<const float4*>(src) + (t * 16 + dgrp * 4 + c);
    const float THR = -1.45f;

    if (tid < G) scnt[tid] = 0;
    __syncthreads();

    // ---- streaming load + unordered candidate capture (atomic slot grab) ----
    #pragma unroll 1
    for (int it = 0; it < 64; it += 8) {
        float4 buf[8];
        #pragma unroll
        for (int u = 0; u < 8; u++) {
            int r = (it + u) * 64 + (tid >> 2);
            buf[u] = __ldg(p + (size_t)r * (NCOL / 4));
        }
        #pragma unroll
        for (int u = 0; u < 8; u++) {
            float vv[4] = {buf[u].x, buf[u].y, buf[u].z, buf[u].w};
            #pragma unroll
            for (int jj = 0; jj < 4; jj++) {
                float v = vv[jj];
                if (v < THR) {
                    int col = c * 4 + jj;
                    unsigned slot = atomicAdd(&scnt[col], 1u);
                    if (slot < CAPC) seg[col * CAPC + slot] = key_of(v);
                }
            }
        }
    }
    __syncthreads();

    // ---- select: warp w owns columns w and w+8, flat candidate arrays ----
    unsigned* h = hist + w * 256;
    const unsigned lmlt = (1u << lane) - 1u;

    for (int cc2 = 0; cc2 < 2; cc2++) {
        const int col = w + cc2 * NWARP;
        unsigned* colb = seg + col * CAPC;
        const int cnt0 = (int)scnt[col];

        unsigned prefix = 0;
        int k = KRANK;

        if (cnt0 > KRANK && cnt0 <= CAPC) {
            int cntf = cnt0;
            for (int shift = 24; shift >= 0; shift -= 8) {
                #pragma unroll
                for (int i = 0; i < 8; i++) h[i * 32 + lane] = 0;
                __syncwarp();
                for (int i0 = 0; i0 < cntf; i0 += 32) {
                    int i = i0 + lane;
                    bool a = i < cntf;
                    unsigned key = a ? colb[i] : 0u;
                    unsigned m = __ballot_sync(0xffffffffu, a);
                    if (a) {
                        unsigned bin = (key >> shift) & 255u;
                        unsigned peers = __match_any_sync(m, bin);
                        if (lane == __ffs(peers) - 1) h[bin] += __popc(peers);
                    }
                }
                __syncwarp();
                unsigned c8[8];
                #pragma unroll
                for (int i = 0; i < 8; i++) c8[i] = h[lane * 8 + i];
                unsigned bucket = find_bucket(c8, k, lane);
                prefix |= bucket << shift;
                if (shift > 0) {
                    // in-place compaction; writes never pass the read frontier
                    int np = 0;
                    for (int i0 = 0; i0 < cntf; i0 += 32) {
                        int i = i0 + lane;
                        bool a = i < cntf;
                        unsigned key = a ? colb[i] : 0u;
                        bool ok = a && (((key >> shift) & 255u) == bucket);
                        unsigned m = __ballot_sync(0xffffffffu, ok);
                        if (ok) colb[np + __popc(m & lmlt)] = key;
                        np += __popc(m);
                    }
                    cntf = np;
                }
            }
        } else {
            // exact fallback (astronomically rare): 4-pass radix re-reading global
            const int cglob = t * 64 + dgrp * 16 + col;
            for (int shift = 24; shift >= 0; shift -= 8) {
                #pragma unroll
                for (int i = 0; i < 8; i++) h[i * 32 + lane] = 0;
                __syncwarp();
                for (int i = lane; i < NB; i += 32) {
                    unsigned key = key_of(__ldg(src + (size_t)i * NCOL + cglob));
                    bool act = (shift == 24) ||
                               ((key >> (shift + 8)) == (prefix >> (shift + 8)));
                    unsigned m = __ballot_sync(0xffffffffu, act);
                    if (act) {
                        unsigned bin = (key >> shift) & 255u;
                        unsigned peers = __match_any_sync(m, bin);
                        if (lane == __ffs(peers) - 1) h[bin] += __popc(peers);
                    }
                }
                __syncwarp();
                unsigned c8[8];
                #pragma unroll
                for (int i = 0; i < 8; i++) c8[i] = h[lane * 8 + i];
                unsigned bucket = find_bucket(c8, k, lane);
                prefix |= bucket << shift;
            }
        }

        if (lane == 0)
            g_var[tensor * NCOL + t * ND + dgrp * G + col] = float_of(prefix);
    }
}

// 16 blocks x 1024 threads: deterministic partial sums into fixed slots
__global__ void reduce_part(void) {
    const int tid  = threadIdx.x;
    const int lane = tid & 31;
    const int wid  = tid >> 5;
    const int i    = blockIdx.x * 1024 + tid;

    float vf = g_var[i];
    float vr = g_var[NCOL + i];
    float d  = fabsf(vf - vr);
    double a = (double)d;
    double r = (double)(d / (fabsf(vr) + 1e-8f));

    #pragma unroll
    for (int off = 16; off > 0; off >>= 1) {
        a += __shfl_down_sync(0xffffffffu, a, off);
        r += __shfl_down_sync(0xffffffffu, r, off);
    }
    __shared__ double sa[32], sr[32];
    if (lane == 0) { sa[wid] = a; sr[wid] = r; }
    __syncthreads();
    if (tid < 32) {
        a = sa[tid]; r = sr[tid];
        #pragma unroll
        for (int off = 16; off > 0; off >>= 1) {
            a += __shfl_down_sync(0xffffffffu, a, off);
            r += __shfl_down_sync(0xffffffffu, r, off);
        }
        if (tid == 0) { g_pa[blockIdx.x] = a; g_pr[blockIdx.x] = r; }
    }
}

// single thread: fixed-order final sum -> bitwise deterministic
__global__ void finalize_kernel(float* __restrict__ out) {
    double a = 0.0, r = 0.0;
    #pragma unroll
    for (int i = 0; i < 16; i++) { a += g_pa[i]; r += g_pr[i]; }
    out[0] = (float)(a / (double)NCOL);
    out[1] = (float)(r / (double)NCOL);
}

extern "C" void kernel_launch(void* const* d_in, const int* in_sizes, int n_in,
                              void* d_out, int out_size) {
    const float* xf = (const float*)d_in[0];
    const float* xr = (const float*)d_in[1];
    const int smem_bytes = (G * CAPC + G + NWARP * 256) * 4;  // 36928
    cudaFuncSetAttribute(select_kernel,
                         cudaFuncAttributeMaxDynamicSharedMemorySize, smem_bytes);
    select_kernel<<<2 * NT * (ND / G), NTHREADS, smem_bytes>>>(xf, xr);
    reduce_part<<<16, 1024>>>();
    finalize_kernel<<<1, 1>>>((float*)d_out);
}

// round 4
// speedup vs baseline: 6.1005x; 1.0397x over previous
#include <cuda_runtime.h>

#define NB       4096        // batch (selection axis)
#define NT       256         // T
#define ND       64          // D
#define NCOL     (NT * ND)   // 16384 columns per tensor
#define KRANK    204         // int(0.05 * 4096), 0-based rank
#define G        16          // columns per block (4 float4 columns = 64 B/row)
#define CAPC     416         // flat candidate capacity per column (mean 301, sd 16.7)
#define NTHREADS 256
#define NWARP    8

__device__ float  g_var[2 * NCOL];
__device__ double g_pa[16];
__device__ double g_pr[16];

static __device__ __forceinline__ unsigned key_of(float f) {
    unsigned u = __float_as_uint(f);
    unsigned mask = (unsigned)((int)u >> 31) | 0x80000000u;
    return u ^ mask;  // monotone: key order == float ascending order
}
static __device__ __forceinline__ float float_of(unsigned k) {
    unsigned mask = (k & 0x80000000u) ? 0x80000000u : 0xFFFFFFFFu;
    return __uint_as_float(k ^ mask);
}

// find the 256-bin bucket containing 0-based rank k; k becomes rank-in-bucket.
// cc[i] = count of bin (lane*8 + i). Warp-collective.
static __device__ __forceinline__ unsigned find_bucket(const unsigned cc[8], int& kk, int lane) {
    unsigned lanesum = 0;
    #pragma unroll
    for (int i = 0; i < 8; i++) lanesum += cc[i];
    unsigned s = lanesum;
    #pragma unroll
    for (int off = 1; off < 32; off <<= 1) {
        unsigned n = __shfl_up_sync(0xffffffffu, s, off);
        if (lane >= off) s += n;
    }
    unsigned run = s - lanesum;  // exclusive prefix over lanes
    int bucket = -1, nk = 0;
    #pragma unroll
    for (int i = 0; i < 8; i++) {
        if (bucket < 0 && (unsigned)kk >= run && (unsigned)kk < run + cc[i]) {
            bucket = lane * 8 + i;
            nk = kk - (int)run;
        }
        run += cc[i];
    }
    unsigned bal = __ballot_sync(0xffffffffu, bucket >= 0);
    int srcl = __ffs(bal) - 1;
    int bb = __shfl_sync(0xffffffffu, bucket, srcl);
    kk = __shfl_sync(0xffffffffu, nk, srcl);
    return (unsigned)bb;
}

__global__ void __launch_bounds__(NTHREADS, 5)
select_kernel(const float* __restrict__ xf, const float* __restrict__ xr) {
    extern __shared__ unsigned smem[];
    unsigned* seg  = smem;                       // [G][CAPC]  flat per-column candidates
    unsigned* scnt = smem + G * CAPC;            // [G]
    unsigned* hist = scnt + G;                   // [NWARP][256]

    const int tid  = threadIdx.x;
    const int lane = tid & 31;
    const int w    = tid >> 5;

    const int bid    = blockIdx.x;               // 2048 blocks
    const int tensor = bid >> 10;
    const int rem    = bid & 1023;
    const int t      = rem >> 2;
    const int dgrp   = rem & 3;                  // which group of 16 columns

    const float* src = tensor ? xr : xf;
    const int c = tid & 3;                       // this thread's float4-column (0..3)
    const float4* p = reinterpret_cast<const float4*>(src) + (t * 16 + dgrp * 4 + c);
    const float THR = -1.45f;

    if (tid < G) scnt[tid] = 0;
    __syncthreads();

    // ---- streaming load + unordered candidate capture (atomic slot grab) ----
    #pragma unroll 1
    for (int it = 0; it < 64; it += 4) {
        float4 buf[4];
        #pragma unroll
        for (int u = 0; u < 4; u++) {
            int r = (it + u) * 64 + (tid >> 2);
            buf[u] = __ldg(p + (size_t)r * (NCOL / 4));
        }
        #pragma unroll
        for (int u = 0; u < 4; u++) {
            float vv[4] = {buf[u].x, buf[u].y, buf[u].z, buf[u].w};
            #pragma unroll
            for (int jj = 0; jj < 4; jj++) {
                float v = vv[jj];
                if (v < THR) {
                    int col = c * 4 + jj;
                    unsigned slot = atomicAdd(&scnt[col], 1u);
                    if (slot < CAPC) seg[col * CAPC + slot] = key_of(v);
                }
            }
        }
    }
    __syncthreads();

    // ---- select: warp w owns columns w and w+8, flat candidate arrays ----
    unsigned* h = hist + w * 256;
    const unsigned lmlt = (1u << lane) - 1u;

    for (int cc2 = 0; cc2 < 2; cc2++) {
        const int col = w + cc2 * NWARP;
        unsigned* colb = seg + col * CAPC;
        const int cnt0 = (int)scnt[col];

        unsigned prefix = 0;
        int k = KRANK;

        if (cnt0 > KRANK && cnt0 <= CAPC) {
            int cntf = cnt0;
            for (int shift = 24; shift >= 0; shift -= 8) {
                #pragma unroll
                for (int i = 0; i < 8; i++) h[i * 32 + lane] = 0;
                __syncwarp();
                for (int i0 = 0; i0 < cntf; i0 += 32) {
                    int i = i0 + lane;
                    bool a = i < cntf;
                    unsigned key = a ? colb[i] : 0u;
                    unsigned m = __ballot_sync(0xffffffffu, a);
                    if (a) {
                        unsigned bin = (key >> shift) & 255u;
                        unsigned peers = __match_any_sync(m, bin);
                        if (lane == __ffs(peers) - 1) h[bin] += __popc(peers);
                    }
                }
                __syncwarp();
                unsigned c8[8];
                #pragma unroll
                for (int i = 0; i < 8; i++) c8[i] = h[lane * 8 + i];
                unsigned bucket = find_bucket(c8, k, lane);
                prefix |= bucket << shift;
                if (shift > 0) {
                    // in-place compaction; writes never pass the read frontier
                    int np = 0;
                    for (int i0 = 0; i0 < cntf; i0 += 32) {
                        int i = i0 + lane;
                        bool a = i < cntf;
                        unsigned key = a ? colb[i] : 0u;
                        bool ok = a && (((key >> shift) & 255u) == bucket);
                        unsigned m = __ballot_sync(0xffffffffu, ok);
                        if (ok) colb[np + __popc(m & lmlt)] = key;
                        np += __popc(m);
                    }
                    cntf = np;
                }
            }
        } else {
            // exact fallback (astronomically rare): 4-pass radix re-reading global
            const int cglob = t * 64 + dgrp * 16 + col;
            for (int shift = 24; shift >= 0; shift -= 8) {
                #pragma unroll
                for (int i = 0; i < 8; i++) h[i * 32 + lane] = 0;
                __syncwarp();
                for (int i = lane; i < NB; i += 32) {
                    unsigned key = key_of(__ldg(src + (size_t)i * NCOL + cglob));
                    bool act = (shift == 24) ||
                               ((key >> (shift + 8)) == (prefix >> (shift + 8)));
                    unsigned m = __ballot_sync(0xffffffffu, act);
                    if (act) {
                        unsigned bin = (key >> shift) & 255u;
                        unsigned peers = __match_any_sync(m, bin);
                        if (lane == __ffs(peers) - 1) h[bin] += __popc(peers);
                    }
                }
                __syncwarp();
                unsigned c8[8];
                #pragma unroll
                for (int i = 0; i < 8; i++) c8[i] = h[lane * 8 + i];
                unsigned bucket = find_bucket(c8, k, lane);
                prefix |= bucket << shift;
            }
        }

        if (lane == 0)
            g_var[tensor * NCOL + t * ND + dgrp * G + col] = float_of(prefix);
    }
}

// 16 blocks x 1024 threads: deterministic partial sums into fixed slots
__global__ void reduce_part(void) {
    const int tid  = threadIdx.x;
    const int lane = tid & 31;
    const int wid  = tid >> 5;
    const int i    = blockIdx.x * 1024 + tid;

    float vf = g_var[i];
    float vr = g_var[NCOL + i];
    float d  = fabsf(vf - vr);
    double a = (double)d;
    double r = (double)(d / (fabsf(vr) + 1e-8f));

    #pragma unroll
    for (int off = 16; off > 0; off >>= 1) {
        a += __shfl_down_sync(0xffffffffu, a, off);
        r += __shfl_down_sync(0xffffffffu, r, off);
    }
    __shared__ double sa[32], sr[32];
    if (lane == 0) { sa[wid] = a; sr[wid] = r; }
    __syncthreads();
    if (tid < 32) {
        a = sa[tid]; r = sr[tid];
        #pragma unroll
        for (int off = 16; off > 0; off >>= 1) {
            a += __shfl_down_sync(0xffffffffu, a, off);
            r += __shfl_down_sync(0xffffffffu, r, off);
        }
        if (tid == 0) { g_pa[blockIdx.x] = a; g_pr[blockIdx.x] = r; }
    }
}

// single thread: fixed-order final sum -> bitwise deterministic
__global__ void finalize_kernel(float* __restrict__ out) {
    double a = 0.0, r = 0.0;
    #pragma unroll
    for (int i = 0; i < 16; i++) { a += g_pa[i]; r += g_pr[i]; }
    out[0] = (float)(a / (double)NCOL);
    out[1] = (float)(r / (double)NCOL);
}

extern "C" void kernel_launch(void* const* d_in, const int* in_sizes, int n_in,
                              void* d_out, int out_size) {
    const float* xf = (const float*)d_in[0];
    const float* xr = (const float*)d_in[1];
    const int smem_bytes = (G * CAPC + G + NWARP * 256) * 4;  // 34880
    cudaFuncSetAttribute(select_kernel,
                         cudaFuncAttributeMaxDynamicSharedMemorySize, smem_bytes);
    select_kernel<<<2 * NT * (ND / G), NTHREADS, smem_bytes>>>(xf, xr);
    reduce_part<<<16, 1024>>>();
    finalize_kernel<<<1, 1>>>((float*)d_out);
}